// round 2
// baseline (speedup 1.0000x reference)
#include <cuda_runtime.h>
#include <cuda_bf16.h>
#include <cstdint>

#define NTOK 65536
#define DIM  512
#define NEXP 8

// ---------------- device scratch (static globals: allocs are forbidden) ----------------
__device__ unsigned       g_cnt[NEXP];
__device__ int            g_tok[NEXP * NTOK];          // token | (kk<<16)
__device__ float          g_wt [NEXP * NTOK];          // gate weight per slot
__device__ __nv_bfloat16  g_xhi[(size_t)NTOK * DIM];
__device__ __nv_bfloat16  g_xlo[(size_t)NTOK * DIM];
__device__ __nv_bfloat16  g_whi[(size_t)NEXP * DIM * DIM];
__device__ __nv_bfloat16  g_wlo[(size_t)NEXP * DIM * DIM];
__device__ float          g_scr[(size_t)2 * NTOK * DIM];   // row = kk*NTOK + token

// ---------------- helpers ----------------
__device__ __forceinline__ uint32_t pk2(__nv_bfloat16 a, __nv_bfloat16 b) {
    return (uint32_t)__bfloat16_as_ushort(a) | ((uint32_t)__bfloat16_as_ushort(b) << 16);
}

__device__ __forceinline__ void ldmx4(uint32_t* r, uint32_t addr) {
    asm volatile("ldmatrix.sync.aligned.m8n8.x4.shared.b16 {%0,%1,%2,%3}, [%4];\n"
                 : "=r"(r[0]), "=r"(r[1]), "=r"(r[2]), "=r"(r[3]) : "r"(addr));
}

__device__ __forceinline__ void mma16816(float* c, const uint32_t* a, uint32_t b0, uint32_t b1) {
    asm volatile("mma.sync.aligned.m16n8k16.row.col.f32.bf16.bf16.f32 "
                 "{%0,%1,%2,%3}, {%4,%5,%6,%7}, {%8,%9}, {%0,%1,%2,%3};\n"
                 : "+f"(c[0]), "+f"(c[1]), "+f"(c[2]), "+f"(c[3])
                 : "r"(a[0]), "r"(a[1]), "r"(a[2]), "r"(a[3]), "r"(b0), "r"(b1));
}

// ---------------- kernel 0: reset counters ----------------
__global__ void reset_kernel() {
    if (threadIdx.x < NEXP) g_cnt[threadIdx.x] = 0;
}

// ---------------- kernel 1: split W -> bf16 hi/lo ----------------
__global__ void prepw_kernel(const float* __restrict__ W) {
    int idx = blockIdx.x * blockDim.x + threadIdx.x;   // float4 index over E*D*D/4
    float4 v = reinterpret_cast<const float4*>(W)[idx];
    __nv_bfloat16 h0 = __float2bfloat16(v.x), h1 = __float2bfloat16(v.y);
    __nv_bfloat16 h2 = __float2bfloat16(v.z), h3 = __float2bfloat16(v.w);
    __nv_bfloat16 l0 = __float2bfloat16(v.x - __bfloat162float(h0));
    __nv_bfloat16 l1 = __float2bfloat16(v.y - __bfloat162float(h1));
    __nv_bfloat16 l2 = __float2bfloat16(v.z - __bfloat162float(h2));
    __nv_bfloat16 l3 = __float2bfloat16(v.w - __bfloat162float(h3));
    uint2 uhi; uhi.x = pk2(h0, h1); uhi.y = pk2(h2, h3);
    uint2 ulo; ulo.x = pk2(l0, l1); ulo.y = pk2(l2, l3);
    reinterpret_cast<uint2*>(g_whi)[idx] = uhi;
    reinterpret_cast<uint2*>(g_wlo)[idx] = ulo;
}

// ---------------- kernel 2: gate (scores, top2, softmax, buckets) + x split ----------------
__global__ __launch_bounds__(256) void gate_kernel(const float* __restrict__ x,
                                                   const float* __restrict__ Wg,
                                                   const float* __restrict__ bg) {
    __shared__ float sWg[NEXP * DIM];
    const int tid = threadIdx.x;
    for (int i = tid; i < NEXP * DIM / 4; i += 256)
        reinterpret_cast<float4*>(sWg)[i] = reinterpret_cast<const float4*>(Wg)[i];
    __syncthreads();

    const int wid = tid >> 5, lane = tid & 31;
    const int t = blockIdx.x * 8 + wid;

    const float4* xr = reinterpret_cast<const float4*>(x) + (size_t)t * (DIM / 4);
    float acc[NEXP];
#pragma unroll
    for (int e = 0; e < NEXP; e++) acc[e] = 0.f;

#pragma unroll
    for (int j = 0; j < 4; j++) {
        const int i4 = lane + 32 * j;           // float4 index in row [0,128)
        float4 v = xr[i4];
#pragma unroll
        for (int e = 0; e < NEXP; e++) {
            float4 wv = reinterpret_cast<const float4*>(sWg)[e * (DIM / 4) + i4];
            acc[e] += v.x * wv.x;
            acc[e] += v.y * wv.y;
            acc[e] += v.z * wv.z;
            acc[e] += v.w * wv.w;
        }
        // bf16 hi/lo split of x, written back for the expert GEMM
        __nv_bfloat16 h0 = __float2bfloat16(v.x), h1 = __float2bfloat16(v.y);
        __nv_bfloat16 h2 = __float2bfloat16(v.z), h3 = __float2bfloat16(v.w);
        __nv_bfloat16 l0 = __float2bfloat16(v.x - __bfloat162float(h0));
        __nv_bfloat16 l1 = __float2bfloat16(v.y - __bfloat162float(h1));
        __nv_bfloat16 l2 = __float2bfloat16(v.z - __bfloat162float(h2));
        __nv_bfloat16 l3 = __float2bfloat16(v.w - __bfloat162float(h3));
        uint2 uhi; uhi.x = pk2(h0, h1); uhi.y = pk2(h2, h3);
        uint2 ulo; ulo.x = pk2(l0, l1); ulo.y = pk2(l2, l3);
        reinterpret_cast<uint2*>(g_xhi)[(size_t)t * (DIM / 4) + i4] = uhi;
        reinterpret_cast<uint2*>(g_xlo)[(size_t)t * (DIM / 4) + i4] = ulo;
    }

#pragma unroll
    for (int e = 0; e < NEXP; e++) {
        float s = acc[e];
        s += __shfl_xor_sync(0xffffffffu, s, 16);
        s += __shfl_xor_sync(0xffffffffu, s, 8);
        s += __shfl_xor_sync(0xffffffffu, s, 4);
        s += __shfl_xor_sync(0xffffffffu, s, 2);
        s += __shfl_xor_sync(0xffffffffu, s, 1);
        acc[e] = s;
    }

    if (lane == 0) {
        float v[NEXP];
#pragma unroll
        for (int e = 0; e < NEXP; e++) v[e] = acc[e] + bg[e];
        int e0 = 0;
#pragma unroll
        for (int e = 1; e < NEXP; e++) if (v[e] > v[e0]) e0 = e;   // ties: lower index (matches top_k)
        int e1 = (e0 == 0) ? 1 : 0;
#pragma unroll
        for (int e = 0; e < NEXP; e++) if (e != e0 && v[e] > v[e1]) e1 = e;
        float d  = expf(v[e1] - v[e0]);
        float w0 = 1.f / (1.f + d);
        float w1 = 1.f - w0;

        unsigned p0 = atomicAdd(&g_cnt[e0], 1u);
        g_tok[e0 * NTOK + p0] = t;                 // kk = 0
        g_wt [e0 * NTOK + p0] = w0;
        unsigned p1 = atomicAdd(&g_cnt[e1], 1u);
        g_tok[e1 * NTOK + p1] = t | (1 << 16);     // kk = 1
        g_wt [e1 * NTOK + p1] = w1;
    }
}

// ---------------- kernel 3: grouped expert GEMM (bf16-split, 3x mma.sync) ----------------
// Tile: BM=128 tokens x BN=128 outputs, BK=16. 512 threads = 16 warps (4m x 4n),
// warp tile 32x32. grid = (NTOK/128, NEXP, DIM/128).
__global__ __launch_bounds__(512, 1) void moe_gemm_kernel(const float* __restrict__ bias) {
    __shared__ __nv_bfloat16 As[2][128][24];   // [hi/lo][row][k+pad]
    __shared__ __nv_bfloat16 Bs[2][128][24];
    __shared__ int   s_tok[128];
    __shared__ int   s_dst[128];
    __shared__ float s_wt [128];

    const int e  = blockIdx.y;
    const unsigned cnt = g_cnt[e];
    const int m0 = blockIdx.x * 128;
    if ((unsigned)m0 >= cnt) return;
    const int valid = min(128, (int)(cnt - m0));
    const int n0 = blockIdx.z * 128;

    const int tid  = threadIdx.x;
    const int lane = tid & 31, wid = tid >> 5;
    const int warp_m = wid & 3, warp_n = wid >> 2;

    if (tid < 128) {
        int raw = 0; float w = 0.f;
        if (tid < valid) { raw = g_tok[e * NTOK + m0 + tid]; w = g_wt[e * NTOK + m0 + tid]; }
        int t = raw & 0xFFFF;
        s_tok[tid] = t;
        s_dst[tid] = (raw >> 16) * NTOK + t;   // kk*NTOK + token
        s_wt [tid] = w;
    }
    __syncthreads();

    // staging: one 16B job per thread for A and for B
    const int split = tid >> 8;          // 0 hi, 1 lo
    const int srow  = (tid & 255) >> 1;
    const int shalf = tid & 1;
    const __nv_bfloat16* a_base = split ? g_xlo : g_xhi;
    const __nv_bfloat16* w_base = split ? g_wlo : g_whi;
    const uint4* a_src = reinterpret_cast<const uint4*>(a_base + (size_t)s_tok[srow] * DIM + shalf * 8);
    const uint4* b_src = reinterpret_cast<const uint4*>(w_base + (size_t)e * DIM * DIM + (size_t)(n0 + srow) * DIM + shalf * 8);
    uint4* a_dst = reinterpret_cast<uint4*>(&As[split][srow][shalf * 8]);
    uint4* b_dst = reinterpret_cast<uint4*>(&Bs[split][srow][shalf * 8]);

    // ldmatrix addresses (fixed across k loop)
    const int aRow = ((lane >> 3) & 1) * 8 + (lane & 7);
    const int aCol = ((lane >> 4) & 1) * 8;
    const int bRow = ((lane >> 4) & 1) * 8 + (lane & 7);
    const int bCol = ((lane >> 3) & 1) * 8;
    uint32_t aAddr[2][2], bAddr[2][2];
#pragma unroll
    for (int s = 0; s < 2; s++) {
#pragma unroll
        for (int mt = 0; mt < 2; mt++)
            aAddr[s][mt] = (uint32_t)__cvta_generic_to_shared(&As[s][warp_m * 32 + mt * 16 + aRow][aCol]);
#pragma unroll
        for (int pr = 0; pr < 2; pr++)
            bAddr[s][pr] = (uint32_t)__cvta_generic_to_shared(&Bs[s][warp_n * 32 + pr * 16 + bRow][bCol]);
    }

    float acc[2][4][4];
#pragma unroll
    for (int a = 0; a < 2; a++)
#pragma unroll
        for (int b2 = 0; b2 < 4; b2++)
#pragma unroll
            for (int c = 0; c < 4; c++) acc[a][b2][c] = 0.f;

    uint4 pa = a_src[0];
    uint4 pb = b_src[0];

    for (int k0 = 0; k0 < DIM; k0 += 16) {
        *a_dst = pa;
        *b_dst = pb;
        __syncthreads();
        if (k0 + 16 < DIM) {
            const int off = (k0 + 16) >> 3;
            pa = a_src[off];
            pb = b_src[off];
        }
        uint32_t ah[2][4], al[2][4];
        ldmx4(ah[0], aAddr[0][0]); ldmx4(ah[1], aAddr[0][1]);
        ldmx4(al[0], aAddr[1][0]); ldmx4(al[1], aAddr[1][1]);
#pragma unroll
        for (int pr = 0; pr < 2; pr++) {
            uint32_t bh[4], bl[4];
            ldmx4(bh, bAddr[0][pr]);
            ldmx4(bl, bAddr[1][pr]);
            const int nt = pr * 2;
            // hi*hi
            mma16816(acc[0][nt],     ah[0], bh[0], bh[1]);
            mma16816(acc[1][nt],     ah[1], bh[0], bh[1]);
            mma16816(acc[0][nt + 1], ah[0], bh[2], bh[3]);
            mma16816(acc[1][nt + 1], ah[1], bh[2], bh[3]);
            // hi*lo
            mma16816(acc[0][nt],     ah[0], bl[0], bl[1]);
            mma16816(acc[1][nt],     ah[1], bl[0], bl[1]);
            mma16816(acc[0][nt + 1], ah[0], bl[2], bl[3]);
            mma16816(acc[1][nt + 1], ah[1], bl[2], bl[3]);
            // lo*hi
            mma16816(acc[0][nt],     al[0], bh[0], bh[1]);
            mma16816(acc[1][nt],     al[1], bh[0], bh[1]);
            mma16816(acc[0][nt + 1], al[0], bh[2], bh[3]);
            mma16816(acc[1][nt + 1], al[1], bh[2], bh[3]);
        }
        __syncthreads();
    }

    // epilogue: out = w * (acc + bias)
    const int g  = lane >> 2;
    const int tg = lane & 3;
#pragma unroll
    for (int mt = 0; mt < 2; mt++) {
        const int r0 = warp_m * 32 + mt * 16 + g;
        const int r1 = r0 + 8;
        const bool ok0 = r0 < valid, ok1 = r1 < valid;
        const float w0 = s_wt[r0], w1 = s_wt[r1];
        const size_t d0 = (size_t)s_dst[r0] * DIM;
        const size_t d1 = (size_t)s_dst[r1] * DIM;
#pragma unroll
        for (int nt = 0; nt < 4; nt++) {
            const int col = n0 + warp_n * 32 + nt * 8 + tg * 2;
            const float2 bb = *reinterpret_cast<const float2*>(bias + e * DIM + col);
            if (ok0) {
                float2 o;
                o.x = w0 * (acc[mt][nt][0] + bb.x);
                o.y = w0 * (acc[mt][nt][1] + bb.y);
                *reinterpret_cast<float2*>(g_scr + d0 + col) = o;
            }
            if (ok1) {
                float2 o;
                o.x = w1 * (acc[mt][nt][2] + bb.x);
                o.y = w1 * (acc[mt][nt][3] + bb.y);
                *reinterpret_cast<float2*>(g_scr + d1 + col) = o;
            }
        }
    }
}

// ---------------- kernel 4: combine the two expert contributions ----------------
__global__ void combine_kernel(float* __restrict__ out) {
    const float4* s = reinterpret_cast<const float4*>(g_scr);
    float4* o = reinterpret_cast<float4*>(out);
    const int total = NTOK * (DIM / 4);
    for (int i = blockIdx.x * blockDim.x + threadIdx.x; i < total; i += gridDim.x * blockDim.x) {
        float4 a = s[i];
        float4 b = s[i + total];
        float4 r;
        r.x = a.x + b.x; r.y = a.y + b.y; r.z = a.z + b.z; r.w = a.w + b.w;
        o[i] = r;
    }
}

// ---------------- launch ----------------
extern "C" void kernel_launch(void* const* d_in, const int* in_sizes, int n_in,
                              void* d_out, int out_size) {
    const float* x  = (const float*)d_in[0];
    const float* W  = (const float*)d_in[1];
    const float* b  = (const float*)d_in[2];
    const float* Wg = (const float*)d_in[3];
    const float* bg = (const float*)d_in[4];
    float* out = (float*)d_out;

    reset_kernel<<<1, 32>>>();
    prepw_kernel<<<(NEXP * DIM * DIM / 4) / 256, 256>>>(W);
    gate_kernel<<<NTOK / 8, 256>>>(x, Wg, bg);
    dim3 grid(NTOK / 128, NEXP, DIM / 128);
    moe_gemm_kernel<<<grid, 512>>>(b);
    combine_kernel<<<8192, 256>>>(out);
}

// round 5
// speedup vs baseline: 1.3328x; 1.3328x over previous
#include <cuda_runtime.h>
#include <cuda_bf16.h>
#include <cstdint>

#define NTOK 65536
#define DIM  512
#define NEXP 8

// GEMM tile config: BM=128 x BN=128, BK=32, 4-stage cp.async pipeline
#define BM 128
#define BN 128
#define BK 32
#define KSTEPS (DIM / BK)          // 16
#define STAGES 4
#define ROWB 80                    // bytes per smem tile row (32 bf16 + pad -> conflict-free)
#define SPLIT_B (128 * ROWB)       // 10240 : one split (hi or lo) of one tile
#define AB_B    (2 * SPLIT_B)      // 20480 : A (hi+lo) or B (hi+lo)
#define BUF_B   (2 * AB_B)         // 40960 : one full stage (A + B)
#define OFF_TOK   0
#define OFF_DST   512
#define OFF_WT    1024
#define OFF_BIAS  1536
#define OFF_TILES 2048
#define GEMM_SMEM (OFF_TILES + STAGES * BUF_B)   // 165888

// ---------------- device scratch ----------------
__device__ unsigned       g_cnt[NEXP];
__device__ int            g_tok[NEXP * NTOK];
__device__ float          g_wt [NEXP * NTOK];
__device__ __nv_bfloat16  g_xhi[(size_t)NTOK * DIM];
__device__ __nv_bfloat16  g_xlo[(size_t)NTOK * DIM];
__device__ __nv_bfloat16  g_whi[(size_t)NEXP * DIM * DIM];
__device__ __nv_bfloat16  g_wlo[(size_t)NEXP * DIM * DIM];
__device__ float          g_scr[(size_t)2 * NTOK * DIM];

// ---------------- helpers ----------------
__device__ __forceinline__ uint32_t pk2(__nv_bfloat16 a, __nv_bfloat16 b) {
    return (uint32_t)__bfloat16_as_ushort(a) | ((uint32_t)__bfloat16_as_ushort(b) << 16);
}
__device__ __forceinline__ uint32_t smem_u32(const void* p) {
    return (uint32_t)__cvta_generic_to_shared(p);
}
__device__ __forceinline__ void cpasync16(uint32_t dst, const void* src) {
    asm volatile("cp.async.cg.shared.global [%0], [%1], 16;\n" :: "r"(dst), "l"(src));
}
__device__ __forceinline__ void cp_commit() { asm volatile("cp.async.commit_group;\n" ::: "memory"); }
__device__ __forceinline__ void cp_wait2()  { asm volatile("cp.async.wait_group 2;\n" ::: "memory"); }

__device__ __forceinline__ void ldmx4(uint32_t* r, uint32_t addr) {
    asm volatile("ldmatrix.sync.aligned.m8n8.x4.shared.b16 {%0,%1,%2,%3}, [%4];\n"
                 : "=r"(r[0]), "=r"(r[1]), "=r"(r[2]), "=r"(r[3]) : "r"(addr));
}
__device__ __forceinline__ void mma16816(float* c, const uint32_t* a, uint32_t b0, uint32_t b1) {
    asm volatile("mma.sync.aligned.m16n8k16.row.col.f32.bf16.bf16.f32 "
                 "{%0,%1,%2,%3}, {%4,%5,%6,%7}, {%8,%9}, {%0,%1,%2,%3};\n"
                 : "+f"(c[0]), "+f"(c[1]), "+f"(c[2]), "+f"(c[3])
                 : "r"(a[0]), "r"(a[1]), "r"(a[2]), "r"(a[3]), "r"(b0), "r"(b1));
}

// ---------------- kernel 0: reset counters ----------------
__global__ void reset_kernel() {
    if (threadIdx.x < NEXP) g_cnt[threadIdx.x] = 0;
}

// ---------------- kernel 1: split W -> bf16 hi/lo ----------------
__global__ void prepw_kernel(const float* __restrict__ W) {
    int idx = blockIdx.x * blockDim.x + threadIdx.x;
    float4 v = reinterpret_cast<const float4*>(W)[idx];
    __nv_bfloat16 h0 = __float2bfloat16(v.x), h1 = __float2bfloat16(v.y);
    __nv_bfloat16 h2 = __float2bfloat16(v.z), h3 = __float2bfloat16(v.w);
    __nv_bfloat16 l0 = __float2bfloat16(v.x - __bfloat162float(h0));
    __nv_bfloat16 l1 = __float2bfloat16(v.y - __bfloat162float(h1));
    __nv_bfloat16 l2 = __float2bfloat16(v.z - __bfloat162float(h2));
    __nv_bfloat16 l3 = __float2bfloat16(v.w - __bfloat162float(h3));
    uint2 uhi; uhi.x = pk2(h0, h1); uhi.y = pk2(h2, h3);
    uint2 ulo; ulo.x = pk2(l0, l1); ulo.y = pk2(l2, l3);
    reinterpret_cast<uint2*>(g_whi)[idx] = uhi;
    reinterpret_cast<uint2*>(g_wlo)[idx] = ulo;
}

// ---------------- kernel 2: gate + x split ----------------
__global__ __launch_bounds__(256) void gate_kernel(const float* __restrict__ x,
                                                   const float* __restrict__ Wg,
                                                   const float* __restrict__ bg) {
    __shared__ float sWg[NEXP * DIM];
    const int tid = threadIdx.x;
    for (int i = tid; i < NEXP * DIM / 4; i += 256)
        reinterpret_cast<float4*>(sWg)[i] = reinterpret_cast<const float4*>(Wg)[i];
    __syncthreads();

    const int wid = tid >> 5, lane = tid & 31;
    const int t = blockIdx.x * 8 + wid;

    const float4* xr = reinterpret_cast<const float4*>(x) + (size_t)t * (DIM / 4);
    float acc[NEXP];
#pragma unroll
    for (int e = 0; e < NEXP; e++) acc[e] = 0.f;

#pragma unroll
    for (int j = 0; j < 4; j++) {
        const int i4 = lane + 32 * j;
        float4 v = xr[i4];
#pragma unroll
        for (int e = 0; e < NEXP; e++) {
            float4 wv = reinterpret_cast<const float4*>(sWg)[e * (DIM / 4) + i4];
            acc[e] += v.x * wv.x;
            acc[e] += v.y * wv.y;
            acc[e] += v.z * wv.z;
            acc[e] += v.w * wv.w;
        }
        __nv_bfloat16 h0 = __float2bfloat16(v.x), h1 = __float2bfloat16(v.y);
        __nv_bfloat16 h2 = __float2bfloat16(v.z), h3 = __float2bfloat16(v.w);
        __nv_bfloat16 l0 = __float2bfloat16(v.x - __bfloat162float(h0));
        __nv_bfloat16 l1 = __float2bfloat16(v.y - __bfloat162float(h1));
        __nv_bfloat16 l2 = __float2bfloat16(v.z - __bfloat162float(h2));
        __nv_bfloat16 l3 = __float2bfloat16(v.w - __bfloat162float(h3));
        uint2 uhi; uhi.x = pk2(h0, h1); uhi.y = pk2(h2, h3);
        uint2 ulo; ulo.x = pk2(l0, l1); ulo.y = pk2(l2, l3);
        reinterpret_cast<uint2*>(g_xhi)[(size_t)t * (DIM / 4) + i4] = uhi;
        reinterpret_cast<uint2*>(g_xlo)[(size_t)t * (DIM / 4) + i4] = ulo;
    }

#pragma unroll
    for (int e = 0; e < NEXP; e++) {
        float s = acc[e];
        s += __shfl_xor_sync(0xffffffffu, s, 16);
        s += __shfl_xor_sync(0xffffffffu, s, 8);
        s += __shfl_xor_sync(0xffffffffu, s, 4);
        s += __shfl_xor_sync(0xffffffffu, s, 2);
        s += __shfl_xor_sync(0xffffffffu, s, 1);
        acc[e] = s;
    }

    if (lane == 0) {
        float v[NEXP];
#pragma unroll
        for (int e = 0; e < NEXP; e++) v[e] = acc[e] + bg[e];
        int e0 = 0;
#pragma unroll
        for (int e = 1; e < NEXP; e++) if (v[e] > v[e0]) e0 = e;
        int e1 = (e0 == 0) ? 1 : 0;
#pragma unroll
        for (int e = 0; e < NEXP; e++) if (e != e0 && v[e] > v[e1]) e1 = e;
        float d  = expf(v[e1] - v[e0]);
        float w0 = 1.f / (1.f + d);
        float w1 = 1.f - w0;

        unsigned p0 = atomicAdd(&g_cnt[e0], 1u);
        g_tok[e0 * NTOK + p0] = t;
        g_wt [e0 * NTOK + p0] = w0;
        unsigned p1 = atomicAdd(&g_cnt[e1], 1u);
        g_tok[e1 * NTOK + p1] = t | (1 << 16);
        g_wt [e1 * NTOK + p1] = w1;
    }
}

// ---------------- kernel 3: grouped expert GEMM, 4-stage cp.async + mma.sync ----------------
// 512 threads = 16 warps (4m x 4n), warp tile 32x32, bf16 hi/lo 3-pass.
__global__ __launch_bounds__(512) void moe_gemm_mma(const float* __restrict__ bias) {
    extern __shared__ char smem[];
    const int e = blockIdx.y;
    const unsigned cnt = g_cnt[e];
    const int m0 = blockIdx.x * BM;
    if ((unsigned)m0 >= cnt) return;
    const int valid = min(BM, (int)(cnt - m0));
    const int n0 = blockIdx.z * BN;

    const int tid  = threadIdx.x;
    const int lane = tid & 31, wid = tid >> 5;
    const int warp_m = wid & 3, warp_n = wid >> 2;
    const uint32_t sb = smem_u32(smem);

    int*   s_tok  = reinterpret_cast<int*>(smem + OFF_TOK);
    int*   s_dst  = reinterpret_cast<int*>(smem + OFF_DST);
    float* s_wt   = reinterpret_cast<float*>(smem + OFF_WT);
    float* s_bias = reinterpret_cast<float*>(smem + OFF_BIAS);

    if (tid < 128) {
        int raw = 0; float w = 0.f;
        if (tid < valid) { raw = g_tok[e * NTOK + m0 + tid]; w = g_wt[e * NTOK + m0 + tid]; }
        int t = raw & 0xFFFF;
        s_tok[tid] = t;
        s_dst[tid] = (raw >> 16) * NTOK + t;
        s_wt [tid] = w;
    } else if (tid < 160) {
        int i = tid - 128;
        reinterpret_cast<float4*>(s_bias)[i] =
            *reinterpret_cast<const float4*>(bias + e * DIM + n0 + i * 4);
    }
    __syncthreads();

    // ---- per-thread loader setup: 4 chunks of 16B per stage (2048 chunks / 512 thr)
    const char* lsrc[4];
    uint32_t    ldst[4];
#pragma unroll
    for (int j = 0; j < 4; j++) {
        const int i     = tid + j * 512;
        const int kind  = i >> 10;          // 0 = A, 1 = B
        const int rem   = i & 1023;
        const int split = rem >> 9;         // 0 = hi, 1 = lo
        const int rem2  = rem & 511;
        const int row   = rem2 >> 2;
        const int c     = rem2 & 3;         // 16B chunk within 64B row
        const __nv_bfloat16* base;
        if (kind == 0)
            base = (split ? g_xlo : g_xhi) + (size_t)s_tok[row] * DIM + c * 8;
        else
            base = (split ? g_wlo : g_whi) + (size_t)e * DIM * DIM + (size_t)(n0 + row) * DIM + c * 8;
        lsrc[j] = reinterpret_cast<const char*>(base);
        ldst[j] = sb + OFF_TILES + kind * AB_B + (split * 128 + row) * ROWB + c * 16;
    }

    // ---- ldmatrix addresses (buf 0, k16 = 0); add bufOff + k16*32 at use
    const int aRow = ((lane >> 3) & 1) * 8 + (lane & 7);
    const int aCol = ((lane >> 4) & 1) * 8;
    const int bRow = ((lane >> 4) & 1) * 8 + (lane & 7);
    const int bCol = ((lane >> 3) & 1) * 8;
    uint32_t aAddr[2][2], bAddr[2][2];
#pragma unroll
    for (int s = 0; s < 2; s++) {
#pragma unroll
        for (int mt = 0; mt < 2; mt++)
            aAddr[s][mt] = sb + OFF_TILES + s * SPLIT_B
                         + (warp_m * 32 + mt * 16 + aRow) * ROWB + aCol * 2;
#pragma unroll
        for (int pr = 0; pr < 2; pr++)
            bAddr[s][pr] = sb + OFF_TILES + AB_B + s * SPLIT_B
                         + (warp_n * 32 + pr * 16 + bRow) * ROWB + bCol * 2;
    }

    float acc[2][4][4];
#pragma unroll
    for (int a = 0; a < 2; a++)
#pragma unroll
        for (int b2 = 0; b2 < 4; b2++)
#pragma unroll
            for (int c = 0; c < 4; c++) acc[a][b2][c] = 0.f;

    // ---- prologue: 3 stages in flight
#pragma unroll
    for (int ks = 0; ks < 3; ks++) {
        const uint32_t bo = ks * BUF_B;
#pragma unroll
        for (int j = 0; j < 4; j++) cpasync16(ldst[j] + bo, lsrc[j] + ks * (BK * 2));
        cp_commit();
    }

    // ---- mainloop: one barrier per 32-K stage
    for (int ks = 0; ks < KSTEPS; ks++) {
        cp_wait2();
        __syncthreads();
        if (ks + 3 < KSTEPS) {
            const uint32_t bo = ((ks + 3) & 3) * BUF_B;
#pragma unroll
            for (int j = 0; j < 4; j++) cpasync16(ldst[j] + bo, lsrc[j] + (ks + 3) * (BK * 2));
        }
        cp_commit();

        const uint32_t bufOff = (ks & 3) * BUF_B;
#pragma unroll
        for (int k16 = 0; k16 < 2; k16++) {
            const uint32_t ko = bufOff + k16 * 32;
            uint32_t ah[2][4], al[2][4];
            ldmx4(ah[0], aAddr[0][0] + ko); ldmx4(ah[1], aAddr[0][1] + ko);
            ldmx4(al[0], aAddr[1][0] + ko); ldmx4(al[1], aAddr[1][1] + ko);
#pragma unroll
            for (int pr = 0; pr < 2; pr++) {
                uint32_t bh[4], bl[4];
                ldmx4(bh, bAddr[0][pr] + ko);
                ldmx4(bl, bAddr[1][pr] + ko);
                const int nt = pr * 2;
                // hi*hi
                mma16816(acc[0][nt],     ah[0], bh[0], bh[1]);
                mma16816(acc[1][nt],     ah[1], bh[0], bh[1]);
                mma16816(acc[0][nt + 1], ah[0], bh[2], bh[3]);
                mma16816(acc[1][nt + 1], ah[1], bh[2], bh[3]);
                // hi*lo
                mma16816(acc[0][nt],     ah[0], bl[0], bl[1]);
                mma16816(acc[1][nt],     ah[1], bl[0], bl[1]);
                mma16816(acc[0][nt + 1], ah[0], bl[2], bl[3]);
                mma16816(acc[1][nt + 1], ah[1], bl[2], bl[3]);
                // lo*hi
                mma16816(acc[0][nt],     al[0], bh[0], bh[1]);
                mma16816(acc[1][nt],     al[1], bh[0], bh[1]);
                mma16816(acc[0][nt + 1], al[0], bh[2], bh[3]);
                mma16816(acc[1][nt + 1], al[1], bh[2], bh[3]);
            }
        }
    }

    // ---- epilogue: out = w * (acc + bias) -> scratch (deterministic slot)
    const int g  = lane >> 2;
    const int tg = lane & 3;
#pragma unroll
    for (int mt = 0; mt < 2; mt++) {
        const int r0 = warp_m * 32 + mt * 16 + g;
        const int r1 = r0 + 8;
        const bool ok0 = r0 < valid, ok1 = r1 < valid;
        const float w0 = s_wt[r0], w1 = s_wt[r1];
        const size_t d0 = (size_t)s_dst[r0] * DIM;
        const size_t d1 = (size_t)s_dst[r1] * DIM;
#pragma unroll
        for (int nt = 0; nt < 4; nt++) {
            const int cloc = warp_n * 32 + nt * 8 + tg * 2;
            const int col  = n0 + cloc;
            const float b0v = s_bias[cloc], b1v = s_bias[cloc + 1];
            if (ok0) {
                float2 o;
                o.x = w0 * (acc[mt][nt][0] + b0v);
                o.y = w0 * (acc[mt][nt][1] + b1v);
                *reinterpret_cast<float2*>(g_scr + d0 + col) = o;
            }
            if (ok1) {
                float2 o;
                o.x = w1 * (acc[mt][nt][2] + b0v);
                o.y = w1 * (acc[mt][nt][3] + b1v);
                *reinterpret_cast<float2*>(g_scr + d1 + col) = o;
            }
        }
    }
}

// ---------------- kernel 4: combine ----------------
__global__ void combine_kernel(float* __restrict__ out) {
    const float4* s = reinterpret_cast<const float4*>(g_scr);
    float4* o = reinterpret_cast<float4*>(out);
    const int total = NTOK * (DIM / 4);
    for (int i = blockIdx.x * blockDim.x + threadIdx.x; i < total; i += gridDim.x * blockDim.x) {
        float4 a = s[i];
        float4 b = s[i + total];
        float4 r;
        r.x = a.x + b.x; r.y = a.y + b.y; r.z = a.z + b.z; r.w = a.w + b.w;
        o[i] = r;
    }
}

// ---------------- launch ----------------
extern "C" void kernel_launch(void* const* d_in, const int* in_sizes, int n_in,
                              void* d_out, int out_size) {
    const float* x  = (const float*)d_in[0];
    const float* W  = (const float*)d_in[1];
    const float* b  = (const float*)d_in[2];
    const float* Wg = (const float*)d_in[3];
    const float* bg = (const float*)d_in[4];
    float* out = (float*)d_out;

    cudaFuncSetAttribute(moe_gemm_mma, cudaFuncAttributeMaxDynamicSharedMemorySize, GEMM_SMEM);

    reset_kernel<<<1, 32>>>();
    prepw_kernel<<<(NEXP * DIM * DIM / 4) / 256, 256>>>(W);
    gate_kernel<<<NTOK / 8, 256>>>(x, Wg, bg);
    dim3 grid(NTOK / BM, NEXP, DIM / BN);
    moe_gemm_mma<<<grid, 512, GEMM_SMEM>>>(b);
    combine_kernel<<<8192, 256>>>(out);
}

// round 6
// speedup vs baseline: 2.4858x; 1.8652x over previous
#include <cuda_runtime.h>
#include <cuda_bf16.h>
#include <cuda_fp16.h>
#include <cstdint>

#define NTOK 65536
#define DIM  512
#define NEXP 8

// GEMM tile config: BM=128 x BN=128, BK=32, 5-stage cp.async pipeline, fp16 1-pass
#define BM 128
#define BN 128
#define BK 32
#define KSTEPS (DIM / BK)          // 16
#define STAGES 5
#define ROWB 80                    // bytes per smem tile row (32 fp16 + 16B pad)
#define TILE_B (128 * ROWB)        // 10240 : one tile (A or B)
#define BUF_B  (2 * TILE_B)        // 20480 : one stage (A + B)
#define OFF_TOK   0
#define OFF_DST   512
#define OFF_WT    1024
#define OFF_BIAS  1536
#define OFF_TILES 2048
#define GEMM_SMEM (OFF_TILES + STAGES * BUF_B)   // 104448 -> 2 CTAs/SM

// ---------------- device scratch ----------------
__device__ unsigned  g_cnt[NEXP];
__device__ int       g_tok[NEXP * NTOK];
__device__ float     g_wt [NEXP * NTOK];
__device__ __half    g_xh[(size_t)NTOK * DIM];
__device__ __half    g_wh[(size_t)NEXP * DIM * DIM];
__device__ float     g_scr[(size_t)2 * NTOK * DIM];

// ---------------- helpers ----------------
__device__ __forceinline__ uint32_t pkh(__half a, __half b) {
    return (uint32_t)__half_as_ushort(a) | ((uint32_t)__half_as_ushort(b) << 16);
}
__device__ __forceinline__ uint32_t smem_u32(const void* p) {
    return (uint32_t)__cvta_generic_to_shared(p);
}
__device__ __forceinline__ void cpasync16(uint32_t dst, const void* src) {
    asm volatile("cp.async.cg.shared.global [%0], [%1], 16;\n" :: "r"(dst), "l"(src));
}
__device__ __forceinline__ void cp_commit() { asm volatile("cp.async.commit_group;\n" ::: "memory"); }
__device__ __forceinline__ void cp_wait3()  { asm volatile("cp.async.wait_group 3;\n" ::: "memory"); }

__device__ __forceinline__ void ldmx4(uint32_t* r, uint32_t addr) {
    asm volatile("ldmatrix.sync.aligned.m8n8.x4.shared.b16 {%0,%1,%2,%3}, [%4];\n"
                 : "=r"(r[0]), "=r"(r[1]), "=r"(r[2]), "=r"(r[3]) : "r"(addr));
}
__device__ __forceinline__ void mma16816h(float* c, const uint32_t* a, uint32_t b0, uint32_t b1) {
    asm volatile("mma.sync.aligned.m16n8k16.row.col.f32.f16.f16.f32 "
                 "{%0,%1,%2,%3}, {%4,%5,%6,%7}, {%8,%9}, {%0,%1,%2,%3};\n"
                 : "+f"(c[0]), "+f"(c[1]), "+f"(c[2]), "+f"(c[3])
                 : "r"(a[0]), "r"(a[1]), "r"(a[2]), "r"(a[3]), "r"(b0), "r"(b1));
}

// ---------------- kernel 0: reset counters ----------------
__global__ void reset_kernel() {
    if (threadIdx.x < NEXP) g_cnt[threadIdx.x] = 0;
}

// ---------------- kernel 1: W -> fp16 ----------------
__global__ void prepw_kernel(const float* __restrict__ W) {
    int idx = blockIdx.x * blockDim.x + threadIdx.x;   // float4 index over E*D*D/4
    float4 v = reinterpret_cast<const float4*>(W)[idx];
    uint2 u;
    u.x = pkh(__float2half_rn(v.x), __float2half_rn(v.y));
    u.y = pkh(__float2half_rn(v.z), __float2half_rn(v.w));
    reinterpret_cast<uint2*>(g_wh)[idx] = u;
}

// ---------------- kernel 2: gate (scores, top2, softmax, buckets) + x -> fp16 ----------------
__global__ __launch_bounds__(256) void gate_kernel(const float* __restrict__ x,
                                                   const float* __restrict__ Wg,
                                                   const float* __restrict__ bg) {
    __shared__ float sWg[NEXP * DIM];
    const int tid = threadIdx.x;
    for (int i = tid; i < NEXP * DIM / 4; i += 256)
        reinterpret_cast<float4*>(sWg)[i] = reinterpret_cast<const float4*>(Wg)[i];
    __syncthreads();

    const int wid = tid >> 5, lane = tid & 31;
    const int t = blockIdx.x * 8 + wid;

    const float4* xr = reinterpret_cast<const float4*>(x) + (size_t)t * (DIM / 4);
    float acc[NEXP];
#pragma unroll
    for (int e = 0; e < NEXP; e++) acc[e] = 0.f;

#pragma unroll
    for (int j = 0; j < 4; j++) {
        const int i4 = lane + 32 * j;
        float4 v = xr[i4];
#pragma unroll
        for (int e = 0; e < NEXP; e++) {
            float4 wv = reinterpret_cast<const float4*>(sWg)[e * (DIM / 4) + i4];
            acc[e] += v.x * wv.x;
            acc[e] += v.y * wv.y;
            acc[e] += v.z * wv.z;
            acc[e] += v.w * wv.w;
        }
        uint2 u;
        u.x = pkh(__float2half_rn(v.x), __float2half_rn(v.y));
        u.y = pkh(__float2half_rn(v.z), __float2half_rn(v.w));
        reinterpret_cast<uint2*>(g_xh)[(size_t)t * (DIM / 4) + i4] = u;
    }

#pragma unroll
    for (int e = 0; e < NEXP; e++) {
        float s = acc[e];
        s += __shfl_xor_sync(0xffffffffu, s, 16);
        s += __shfl_xor_sync(0xffffffffu, s, 8);
        s += __shfl_xor_sync(0xffffffffu, s, 4);
        s += __shfl_xor_sync(0xffffffffu, s, 2);
        s += __shfl_xor_sync(0xffffffffu, s, 1);
        acc[e] = s;
    }

    if (lane == 0) {
        float v[NEXP];
#pragma unroll
        for (int e = 0; e < NEXP; e++) v[e] = acc[e] + bg[e];
        int e0 = 0;
#pragma unroll
        for (int e = 1; e < NEXP; e++) if (v[e] > v[e0]) e0 = e;
        int e1 = (e0 == 0) ? 1 : 0;
#pragma unroll
        for (int e = 0; e < NEXP; e++) if (e != e0 && v[e] > v[e1]) e1 = e;
        float d  = expf(v[e1] - v[e0]);
        float w0 = 1.f / (1.f + d);
        float w1 = 1.f - w0;

        unsigned p0 = atomicAdd(&g_cnt[e0], 1u);
        g_tok[e0 * NTOK + p0] = t;
        g_wt [e0 * NTOK + p0] = w0;
        unsigned p1 = atomicAdd(&g_cnt[e1], 1u);
        g_tok[e1 * NTOK + p1] = t | (1 << 16);
        g_wt [e1 * NTOK + p1] = w1;
    }
}

// ---------------- kernel 3: grouped expert GEMM, fp16 1-pass, 5-stage cp.async ----------------
// 512 threads = 16 warps (4m x 4n), warp tile 32x32.
__global__ __launch_bounds__(512, 2) void moe_gemm_mma(const float* __restrict__ bias) {
    extern __shared__ char smem[];
    const int e = blockIdx.y;
    const unsigned cnt = g_cnt[e];
    const int m0 = blockIdx.x * BM;
    if ((unsigned)m0 >= cnt) return;
    const int valid = min(BM, (int)(cnt - m0));
    const int n0 = blockIdx.z * BN;

    const int tid  = threadIdx.x;
    const int lane = tid & 31, wid = tid >> 5;
    const int warp_m = wid & 3, warp_n = wid >> 2;
    const uint32_t sb = smem_u32(smem);

    int*   s_tok  = reinterpret_cast<int*>(smem + OFF_TOK);
    int*   s_dst  = reinterpret_cast<int*>(smem + OFF_DST);
    float* s_wt   = reinterpret_cast<float*>(smem + OFF_WT);
    float* s_bias = reinterpret_cast<float*>(smem + OFF_BIAS);

    if (tid < 128) {
        int raw = 0; float w = 0.f;
        if (tid < valid) { raw = g_tok[e * NTOK + m0 + tid]; w = g_wt[e * NTOK + m0 + tid]; }
        int t = raw & 0xFFFF;
        s_tok[tid] = t;
        s_dst[tid] = (raw >> 16) * NTOK + t;
        s_wt [tid] = w;
    } else if (tid < 160) {
        int i = tid - 128;
        reinterpret_cast<float4*>(s_bias)[i] =
            *reinterpret_cast<const float4*>(bias + e * DIM + n0 + i * 4);
    }
    __syncthreads();

    // ---- per-thread loader: 2 chunks of 16B per stage (1024 chunks / 512 thr)
    const char* lsrc[2];
    uint32_t    ldst[2];
#pragma unroll
    for (int j = 0; j < 2; j++) {
        const int i    = tid + j * 512;
        const int kind = i >> 9;           // 0 = A, 1 = B
        const int rem  = i & 511;
        const int row  = rem >> 2;
        const int c    = rem & 3;          // 16B chunk within 64B row
        const __half* base;
        if (kind == 0)
            base = g_xh + (size_t)s_tok[row] * DIM + c * 8;
        else
            base = g_wh + (size_t)e * DIM * DIM + (size_t)(n0 + row) * DIM + c * 8;
        lsrc[j] = reinterpret_cast<const char*>(base);
        ldst[j] = sb + OFF_TILES + kind * TILE_B + row * ROWB + c * 16;
    }

    // ---- ldmatrix base addresses (buf 0, k16 = 0); add bufOff + k16*32 at use
    const int aRow = ((lane >> 3) & 1) * 8 + (lane & 7);
    const int aCol = ((lane >> 4) & 1) * 8;
    const int bRow = ((lane >> 4) & 1) * 8 + (lane & 7);
    const int bCol = ((lane >> 3) & 1) * 8;
    uint32_t aAddr[2], bAddr[2];
#pragma unroll
    for (int mt = 0; mt < 2; mt++)
        aAddr[mt] = sb + OFF_TILES + (warp_m * 32 + mt * 16 + aRow) * ROWB + aCol * 2;
#pragma unroll
    for (int pr = 0; pr < 2; pr++)
        bAddr[pr] = sb + OFF_TILES + TILE_B + (warp_n * 32 + pr * 16 + bRow) * ROWB + bCol * 2;

    float acc[2][4][4];
#pragma unroll
    for (int a = 0; a < 2; a++)
#pragma unroll
        for (int b2 = 0; b2 < 4; b2++)
#pragma unroll
            for (int c = 0; c < 4; c++) acc[a][b2][c] = 0.f;

    // ---- prologue: 4 stages in flight
#pragma unroll
    for (int ks = 0; ks < 4; ks++) {
        const uint32_t bo = ks * BUF_B;
#pragma unroll
        for (int j = 0; j < 2; j++) cpasync16(ldst[j] + bo, lsrc[j] + ks * (BK * 2));
        cp_commit();
    }

    // ---- mainloop: one barrier per 32-K stage
    for (int ks = 0; ks < KSTEPS; ks++) {
        cp_wait3();
        __syncthreads();
        if (ks + 4 < KSTEPS) {
            const uint32_t bo = ((ks + 4) % STAGES) * BUF_B;
#pragma unroll
            for (int j = 0; j < 2; j++) cpasync16(ldst[j] + bo, lsrc[j] + (ks + 4) * (BK * 2));
        }
        cp_commit();

        const uint32_t bufOff = (ks % STAGES) * BUF_B;
#pragma unroll
        for (int k16 = 0; k16 < 2; k16++) {
            const uint32_t ko = bufOff + k16 * 32;
            uint32_t ah[2][4];
            ldmx4(ah[0], aAddr[0] + ko);
            ldmx4(ah[1], aAddr[1] + ko);
#pragma unroll
            for (int pr = 0; pr < 2; pr++) {
                uint32_t bh[4];
                ldmx4(bh, bAddr[pr] + ko);
                const int nt = pr * 2;
                mma16816h(acc[0][nt],     ah[0], bh[0], bh[1]);
                mma16816h(acc[1][nt],     ah[1], bh[0], bh[1]);
                mma16816h(acc[0][nt + 1], ah[0], bh[2], bh[3]);
                mma16816h(acc[1][nt + 1], ah[1], bh[2], bh[3]);
            }
        }
    }

    // ---- epilogue: out = w * (acc + bias) -> scratch (deterministic slot)
    const int g  = lane >> 2;
    const int tg = lane & 3;
#pragma unroll
    for (int mt = 0; mt < 2; mt++) {
        const int r0 = warp_m * 32 + mt * 16 + g;
        const int r1 = r0 + 8;
        const bool ok0 = r0 < valid, ok1 = r1 < valid;
        const float w0 = s_wt[r0], w1 = s_wt[r1];
        const size_t d0 = (size_t)s_dst[r0] * DIM;
        const size_t d1 = (size_t)s_dst[r1] * DIM;
#pragma unroll
        for (int nt = 0; nt < 4; nt++) {
            const int cloc = warp_n * 32 + nt * 8 + tg * 2;
            const int col  = n0 + cloc;
            const float b0v = s_bias[cloc], b1v = s_bias[cloc + 1];
            if (ok0) {
                float2 o;
                o.x = w0 * (acc[mt][nt][0] + b0v);
                o.y = w0 * (acc[mt][nt][1] + b1v);
                *reinterpret_cast<float2*>(g_scr + d0 + col) = o;
            }
            if (ok1) {
                float2 o;
                o.x = w1 * (acc[mt][nt][2] + b0v);
                o.y = w1 * (acc[mt][nt][3] + b1v);
                *reinterpret_cast<float2*>(g_scr + d1 + col) = o;
            }
        }
    }
}

// ---------------- kernel 4: combine ----------------
__global__ void combine_kernel(float* __restrict__ out) {
    const float4* s = reinterpret_cast<const float4*>(g_scr);
    float4* o = reinterpret_cast<float4*>(out);
    const int total = NTOK * (DIM / 4);
    for (int i = blockIdx.x * blockDim.x + threadIdx.x; i < total; i += gridDim.x * blockDim.x) {
        float4 a = s[i];
        float4 b = s[i + total];
        float4 r;
        r.x = a.x + b.x; r.y = a.y + b.y; r.z = a.z + b.z; r.w = a.w + b.w;
        o[i] = r;
    }
}

// ---------------- launch ----------------
extern "C" void kernel_launch(void* const* d_in, const int* in_sizes, int n_in,
                              void* d_out, int out_size) {
    const float* x  = (const float*)d_in[0];
    const float* W  = (const float*)d_in[1];
    const float* b  = (const float*)d_in[2];
    const float* Wg = (const float*)d_in[3];
    const float* bg = (const float*)d_in[4];
    float* out = (float*)d_out;

    cudaFuncSetAttribute(moe_gemm_mma, cudaFuncAttributeMaxDynamicSharedMemorySize, GEMM_SMEM);

    reset_kernel<<<1, 32>>>();
    prepw_kernel<<<(NEXP * DIM * DIM / 4) / 256, 256>>>(W);
    gate_kernel<<<NTOK / 8, 256>>>(x, Wg, bg);
    dim3 grid(NTOK / BM, NEXP, DIM / BN);
    moe_gemm_mma<<<grid, 512, GEMM_SMEM>>>(b);
    combine_kernel<<<8192, 256>>>(out);
}

// round 7
// speedup vs baseline: 2.5484x; 1.0252x over previous
#include <cuda_runtime.h>
#include <cuda_bf16.h>
#include <cuda_fp16.h>
#include <cstdint>

#define NTOK 65536
#define DIM  512
#define NEXP 8

// GEMM tile config: BM=128 x BN=128, BK=32, 5-stage cp.async, fp16 1-pass,
// 4 warps (2m x 2n), warp tile 64x64.
#define BM 128
#define BN 128
#define BK 32
#define KSTEPS (DIM / BK)          // 16
#define STAGES 5
#define ROWB 80                    // bytes per smem tile row (32 fp16 + 16B pad)
#define TILE_B (128 * ROWB)        // 10240 : one tile (A or B)
#define BUF_B  (2 * TILE_B)        // 20480 : one stage (A + B)
#define OFF_TOK   0
#define OFF_DST   512
#define OFF_WT    1024
#define OFF_BIAS  1536
#define OFF_TILES 2048
#define GEMM_SMEM (OFF_TILES + STAGES * BUF_B)   // 104448 -> 2 CTAs/SM

// ---------------- device scratch ----------------
__device__ unsigned  g_cnt[NEXP];
__device__ int       g_tok[NEXP * NTOK];
__device__ float     g_wt [NEXP * NTOK];
__device__ __half    g_xh[(size_t)NTOK * DIM];
__device__ __half    g_wh[(size_t)NEXP * DIM * DIM];
__device__ float     g_scr[(size_t)2 * NTOK * DIM];

// ---------------- helpers ----------------
__device__ __forceinline__ uint32_t pkh(__half a, __half b) {
    return (uint32_t)__half_as_ushort(a) | ((uint32_t)__half_as_ushort(b) << 16);
}
__device__ __forceinline__ uint32_t smem_u32(const void* p) {
    return (uint32_t)__cvta_generic_to_shared(p);
}
__device__ __forceinline__ void cpasync16(uint32_t dst, const void* src) {
    asm volatile("cp.async.cg.shared.global [%0], [%1], 16;\n" :: "r"(dst), "l"(src));
}
__device__ __forceinline__ void cp_commit() { asm volatile("cp.async.commit_group;\n" ::: "memory"); }
__device__ __forceinline__ void cp_wait3()  { asm volatile("cp.async.wait_group 3;\n" ::: "memory"); }

__device__ __forceinline__ void ldmx4(uint32_t* r, uint32_t addr) {
    asm volatile("ldmatrix.sync.aligned.m8n8.x4.shared.b16 {%0,%1,%2,%3}, [%4];\n"
                 : "=r"(r[0]), "=r"(r[1]), "=r"(r[2]), "=r"(r[3]) : "r"(addr));
}
__device__ __forceinline__ void mma16816h(float* c, const uint32_t* a, uint32_t b0, uint32_t b1) {
    asm volatile("mma.sync.aligned.m16n8k16.row.col.f32.f16.f16.f32 "
                 "{%0,%1,%2,%3}, {%4,%5,%6,%7}, {%8,%9}, {%0,%1,%2,%3};\n"
                 : "+f"(c[0]), "+f"(c[1]), "+f"(c[2]), "+f"(c[3])
                 : "r"(a[0]), "r"(a[1]), "r"(a[2]), "r"(a[3]), "r"(b0), "r"(b1));
}

// ---------------- kernel 0: reset counters ----------------
__global__ void reset_kernel() {
    if (threadIdx.x < NEXP) g_cnt[threadIdx.x] = 0;
}

// ---------------- kernel 1: W -> fp16 ----------------
__global__ void prepw_kernel(const float* __restrict__ W) {
    int idx = blockIdx.x * blockDim.x + threadIdx.x;
    float4 v = reinterpret_cast<const float4*>(W)[idx];
    uint2 u;
    u.x = pkh(__float2half_rn(v.x), __float2half_rn(v.y));
    u.y = pkh(__float2half_rn(v.z), __float2half_rn(v.w));
    reinterpret_cast<uint2*>(g_wh)[idx] = u;
}

// ---------------- kernel 2: gate (scores, top2, softmax, buckets) + x -> fp16 ----------------
__global__ __launch_bounds__(256) void gate_kernel(const float* __restrict__ x,
                                                   const float* __restrict__ Wg,
                                                   const float* __restrict__ bg) {
    __shared__ float sWg[NEXP * DIM];
    const int tid = threadIdx.x;
    for (int i = tid; i < NEXP * DIM / 4; i += 256)
        reinterpret_cast<float4*>(sWg)[i] = reinterpret_cast<const float4*>(Wg)[i];
    __syncthreads();

    const int wid = tid >> 5, lane = tid & 31;
    const int t = blockIdx.x * 8 + wid;

    const float4* xr = reinterpret_cast<const float4*>(x) + (size_t)t * (DIM / 4);
    float acc[NEXP];
#pragma unroll
    for (int e = 0; e < NEXP; e++) acc[e] = 0.f;

#pragma unroll
    for (int j = 0; j < 4; j++) {
        const int i4 = lane + 32 * j;
        float4 v = xr[i4];
#pragma unroll
        for (int e = 0; e < NEXP; e++) {
            float4 wv = reinterpret_cast<const float4*>(sWg)[e * (DIM / 4) + i4];
            acc[e] += v.x * wv.x;
            acc[e] += v.y * wv.y;
            acc[e] += v.z * wv.z;
            acc[e] += v.w * wv.w;
        }
        uint2 u;
        u.x = pkh(__float2half_rn(v.x), __float2half_rn(v.y));
        u.y = pkh(__float2half_rn(v.z), __float2half_rn(v.w));
        reinterpret_cast<uint2*>(g_xh)[(size_t)t * (DIM / 4) + i4] = u;
    }

#pragma unroll
    for (int e = 0; e < NEXP; e++) {
        float s = acc[e];
        s += __shfl_xor_sync(0xffffffffu, s, 16);
        s += __shfl_xor_sync(0xffffffffu, s, 8);
        s += __shfl_xor_sync(0xffffffffu, s, 4);
        s += __shfl_xor_sync(0xffffffffu, s, 2);
        s += __shfl_xor_sync(0xffffffffu, s, 1);
        acc[e] = s;
    }

    if (lane == 0) {
        float v[NEXP];
#pragma unroll
        for (int e = 0; e < NEXP; e++) v[e] = acc[e] + bg[e];
        int e0 = 0;
#pragma unroll
        for (int e = 1; e < NEXP; e++) if (v[e] > v[e0]) e0 = e;
        int e1 = (e0 == 0) ? 1 : 0;
#pragma unroll
        for (int e = 0; e < NEXP; e++) if (e != e0 && v[e] > v[e1]) e1 = e;
        float d  = expf(v[e1] - v[e0]);
        float w0 = 1.f / (1.f + d);
        float w1 = 1.f - w0;

        unsigned p0 = atomicAdd(&g_cnt[e0], 1u);
        g_tok[e0 * NTOK + p0] = t;
        g_wt [e0 * NTOK + p0] = w0;
        unsigned p1 = atomicAdd(&g_cnt[e1], 1u);
        g_tok[e1 * NTOK + p1] = t | (1 << 16);
        g_wt [e1 * NTOK + p1] = w1;
    }
}

// ---------------- kernel 3: grouped expert GEMM, fp16, 4 warps x (64x64) ----------------
__global__ __launch_bounds__(128, 2) void moe_gemm_mma(const float* __restrict__ bias) {
    extern __shared__ char smem[];
    const int e = blockIdx.y;
    const unsigned cnt = g_cnt[e];
    const int m0 = blockIdx.x * BM;
    if ((unsigned)m0 >= cnt) return;
    const int valid = min(BM, (int)(cnt - m0));
    const int n0 = blockIdx.z * BN;

    const int tid  = threadIdx.x;
    const int lane = tid & 31, wid = tid >> 5;
    const int warp_m = wid & 1, warp_n = wid >> 1;
    const uint32_t sb = smem_u32(smem);

    int*   s_tok  = reinterpret_cast<int*>(smem + OFF_TOK);
    int*   s_dst  = reinterpret_cast<int*>(smem + OFF_DST);
    float* s_wt   = reinterpret_cast<float*>(smem + OFF_WT);
    float* s_bias = reinterpret_cast<float*>(smem + OFF_BIAS);

    {
        int raw = 0; float w = 0.f;
        if (tid < valid) { raw = g_tok[e * NTOK + m0 + tid]; w = g_wt[e * NTOK + m0 + tid]; }
        int t = raw & 0xFFFF;
        s_tok[tid] = t;
        s_dst[tid] = (raw >> 16) * NTOK + t;
        s_wt [tid] = w;
        s_bias[tid] = bias[e * DIM + n0 + tid];
    }
    __syncthreads();

    // ---- per-thread loader: 8 chunks of 16B per stage (1024 chunks / 128 thr)
    const char* lsrc[8];
    uint32_t    ldst[8];
#pragma unroll
    for (int j = 0; j < 8; j++) {
        const int i    = tid + j * 128;
        const int kind = i >> 9;           // 0 = A, 1 = B
        const int rem  = i & 511;
        const int row  = rem >> 2;
        const int c    = rem & 3;          // 16B chunk within 64B row
        const __half* base;
        if (kind == 0)
            base = g_xh + (size_t)s_tok[row] * DIM + c * 8;
        else
            base = g_wh + (size_t)e * DIM * DIM + (size_t)(n0 + row) * DIM + c * 8;
        lsrc[j] = reinterpret_cast<const char*>(base);
        ldst[j] = sb + OFF_TILES + kind * TILE_B + row * ROWB + c * 16;
    }

    // ---- ldmatrix base addresses (buf 0, k16 = 0); add bufOff + k16*32 at use
    const int aRow = ((lane >> 3) & 1) * 8 + (lane & 7);
    const int aCol = ((lane >> 4) & 1) * 8;
    const int bRow = ((lane >> 4) & 1) * 8 + (lane & 7);
    const int bCol = ((lane >> 3) & 1) * 8;
    uint32_t aAddr[4], bAddr[4];
#pragma unroll
    for (int mt = 0; mt < 4; mt++)
        aAddr[mt] = sb + OFF_TILES + (warp_m * 64 + mt * 16 + aRow) * ROWB + aCol * 2;
#pragma unroll
    for (int pr = 0; pr < 4; pr++)
        bAddr[pr] = sb + OFF_TILES + TILE_B + (warp_n * 64 + pr * 16 + bRow) * ROWB + bCol * 2;

    float acc[4][8][4];
#pragma unroll
    for (int a = 0; a < 4; a++)
#pragma unroll
        for (int b2 = 0; b2 < 8; b2++)
#pragma unroll
            for (int c = 0; c < 4; c++) acc[a][b2][c] = 0.f;

    // ---- prologue: 4 stages in flight
#pragma unroll
    for (int ks = 0; ks < 4; ks++) {
        const uint32_t bo = ks * BUF_B;
#pragma unroll
        for (int j = 0; j < 8; j++) cpasync16(ldst[j] + bo, lsrc[j] + ks * (BK * 2));
        cp_commit();
    }

    // ---- mainloop: one barrier per 32-K stage
    for (int ks = 0; ks < KSTEPS; ks++) {
        cp_wait3();
        __syncthreads();
        if (ks + 4 < KSTEPS) {
            const uint32_t bo = ((ks + 4) % STAGES) * BUF_B;
#pragma unroll
            for (int j = 0; j < 8; j++) cpasync16(ldst[j] + bo, lsrc[j] + (ks + 4) * (BK * 2));
        }
        cp_commit();

        const uint32_t bufOff = (ks % STAGES) * BUF_B;
#pragma unroll
        for (int k16 = 0; k16 < 2; k16++) {
            const uint32_t ko = bufOff + k16 * 32;
            uint32_t ah[4][4];
#pragma unroll
            for (int mt = 0; mt < 4; mt++) ldmx4(ah[mt], aAddr[mt] + ko);
#pragma unroll
            for (int pr = 0; pr < 4; pr++) {
                uint32_t bh[4];
                ldmx4(bh, bAddr[pr] + ko);
                const int nt = pr * 2;
#pragma unroll
                for (int mt = 0; mt < 4; mt++) {
                    mma16816h(acc[mt][nt],     ah[mt], bh[0], bh[1]);
                    mma16816h(acc[mt][nt + 1], ah[mt], bh[2], bh[3]);
                }
            }
        }
    }

    // ---- epilogue: out = w * (acc + bias) -> scratch (deterministic slot)
    const int g  = lane >> 2;
    const int tg = lane & 3;
#pragma unroll
    for (int mt = 0; mt < 4; mt++) {
        const int r0 = warp_m * 64 + mt * 16 + g;
        const int r1 = r0 + 8;
        const bool ok0 = r0 < valid, ok1 = r1 < valid;
        const float w0 = s_wt[r0], w1 = s_wt[r1];
        const size_t d0 = (size_t)s_dst[r0] * DIM;
        const size_t d1 = (size_t)s_dst[r1] * DIM;
#pragma unroll
        for (int nt = 0; nt < 8; nt++) {
            const int cloc = warp_n * 64 + nt * 8 + tg * 2;
            const int col  = n0 + cloc;
            const float b0v = s_bias[cloc], b1v = s_bias[cloc + 1];
            if (ok0) {
                float2 o;
                o.x = w0 * (acc[mt][nt][0] + b0v);
                o.y = w0 * (acc[mt][nt][1] + b1v);
                *reinterpret_cast<float2*>(g_scr + d0 + col) = o;
            }
            if (ok1) {
                float2 o;
                o.x = w1 * (acc[mt][nt][2] + b0v);
                o.y = w1 * (acc[mt][nt][3] + b1v);
                *reinterpret_cast<float2*>(g_scr + d1 + col) = o;
            }
        }
    }
}

// ---------------- kernel 4: combine ----------------
__global__ void combine_kernel(float* __restrict__ out) {
    const float4* s = reinterpret_cast<const float4*>(g_scr);
    float4* o = reinterpret_cast<float4*>(out);
    const int total = NTOK * (DIM / 4);
    for (int i = blockIdx.x * blockDim.x + threadIdx.x; i < total; i += gridDim.x * blockDim.x) {
        float4 a = s[i];
        float4 b = s[i + total];
        float4 r;
        r.x = a.x + b.x; r.y = a.y + b.y; r.z = a.z + b.z; r.w = a.w + b.w;
        o[i] = r;
    }
}

// ---------------- launch ----------------
extern "C" void kernel_launch(void* const* d_in, const int* in_sizes, int n_in,
                              void* d_out, int out_size) {
    const float* x  = (const float*)d_in[0];
    const float* W  = (const float*)d_in[1];
    const float* b  = (const float*)d_in[2];
    const float* Wg = (const float*)d_in[3];
    const float* bg = (const float*)d_in[4];
    float* out = (float*)d_out;

    cudaFuncSetAttribute(moe_gemm_mma, cudaFuncAttributeMaxDynamicSharedMemorySize, GEMM_SMEM);

    reset_kernel<<<1, 32>>>();
    prepw_kernel<<<(NEXP * DIM * DIM / 4) / 256, 256>>>(W);
    gate_kernel<<<NTOK / 8, 256>>>(x, Wg, bg);
    dim3 grid(NTOK / BM, NEXP, DIM / BN);
    moe_gemm_mma<<<grid, 128, GEMM_SMEM>>>(b);
    combine_kernel<<<8192, 256>>>(out);
}

// round 8
// speedup vs baseline: 2.6691x; 1.0474x over previous
#include <cuda_runtime.h>
#include <cuda_bf16.h>
#include <cuda_fp16.h>
#include <cstdint>

#define NTOK 65536
#define DIM  512
#define NEXP 8

// GEMM tile: BM=128 x BN=128, BK=32, 5-stage cp.async, fp16 1-pass,
// 8 warps (2m x 4n), warp tile 64x32.
#define BM 128
#define BN 128
#define BK 32
#define KSTEPS (DIM / BK)          // 16
#define STAGES 5
#define ROWB 80                    // bytes per smem tile row (32 fp16 + 16B pad)
#define TILE_B (128 * ROWB)        // 10240 : one tile (A or B)
#define BUF_B  (2 * TILE_B)        // 20480 : one stage (A + B)
#define OFF_TOK   0
#define OFF_DST   512
#define OFF_WT    1024
#define OFF_BIAS  1536
#define OFF_TILES 2048
#define GEMM_SMEM (OFF_TILES + STAGES * BUF_B)   // 104448 -> 2 CTAs/SM

// ---------------- device scratch ----------------
__device__ unsigned  g_cnt[NEXP];
__device__ int       g_tok[NEXP * NTOK];
__device__ float     g_wt [NEXP * NTOK];
__device__ __half    g_xh[(size_t)NTOK * DIM];
__device__ __half    g_wh[(size_t)NEXP * DIM * DIM];
__device__ float     g_scr[(size_t)2 * NTOK * DIM];

// ---------------- helpers ----------------
__device__ __forceinline__ uint32_t pkh(__half a, __half b) {
    return (uint32_t)__half_as_ushort(a) | ((uint32_t)__half_as_ushort(b) << 16);
}
__device__ __forceinline__ uint32_t smem_u32(const void* p) {
    return (uint32_t)__cvta_generic_to_shared(p);
}
__device__ __forceinline__ void cpasync16(uint32_t dst, const void* src) {
    asm volatile("cp.async.cg.shared.global [%0], [%1], 16;\n" :: "r"(dst), "l"(src));
}
__device__ __forceinline__ void cp_commit() { asm volatile("cp.async.commit_group;\n" ::: "memory"); }
__device__ __forceinline__ void cp_wait3()  { asm volatile("cp.async.wait_group 3;\n" ::: "memory"); }

__device__ __forceinline__ void ldmx4(uint32_t* r, uint32_t addr) {
    asm volatile("ldmatrix.sync.aligned.m8n8.x4.shared.b16 {%0,%1,%2,%3}, [%4];\n"
                 : "=r"(r[0]), "=r"(r[1]), "=r"(r[2]), "=r"(r[3]) : "r"(addr));
}
__device__ __forceinline__ void mma16816h(float* c, const uint32_t* a, uint32_t b0, uint32_t b1) {
    asm volatile("mma.sync.aligned.m16n8k16.row.col.f32.f16.f16.f32 "
                 "{%0,%1,%2,%3}, {%4,%5,%6,%7}, {%8,%9}, {%0,%1,%2,%3};\n"
                 : "+f"(c[0]), "+f"(c[1]), "+f"(c[2]), "+f"(c[3])
                 : "r"(a[0]), "r"(a[1]), "r"(a[2]), "r"(a[3]), "r"(b0), "r"(b1));
}

// ---------------- kernel 0: reset counters ----------------
__global__ void reset_kernel() {
    if (threadIdx.x < NEXP) g_cnt[threadIdx.x] = 0;
}

// ---------------- kernel 1: W -> fp16 ----------------
__global__ void prepw_kernel(const float* __restrict__ W) {
    int idx = blockIdx.x * blockDim.x + threadIdx.x;
    float4 v = reinterpret_cast<const float4*>(W)[idx];
    uint2 u;
    u.x = pkh(__float2half_rn(v.x), __float2half_rn(v.y));
    u.y = pkh(__float2half_rn(v.z), __float2half_rn(v.w));
    reinterpret_cast<uint2*>(g_wh)[idx] = u;
}

// ---------------- kernel 2: gate (scores, top2, softmax, buckets) + x -> fp16 ----------------
__global__ __launch_bounds__(256) void gate_kernel(const float* __restrict__ x,
                                                   const float* __restrict__ Wg,
                                                   const float* __restrict__ bg) {
    __shared__ float sWg[NEXP * DIM];
    const int tid = threadIdx.x;
    for (int i = tid; i < NEXP * DIM / 4; i += 256)
        reinterpret_cast<float4*>(sWg)[i] = reinterpret_cast<const float4*>(Wg)[i];
    __syncthreads();

    const int wid = tid >> 5, lane = tid & 31;
    const int t = blockIdx.x * 8 + wid;

    const float4* xr = reinterpret_cast<const float4*>(x) + (size_t)t * (DIM / 4);
    float acc[NEXP];
#pragma unroll
    for (int e = 0; e < NEXP; e++) acc[e] = 0.f;

#pragma unroll
    for (int j = 0; j < 4; j++) {
        const int i4 = lane + 32 * j;
        float4 v = xr[i4];
#pragma unroll
        for (int e = 0; e < NEXP; e++) {
            float4 wv = reinterpret_cast<const float4*>(sWg)[e * (DIM / 4) + i4];
            acc[e] += v.x * wv.x;
            acc[e] += v.y * wv.y;
            acc[e] += v.z * wv.z;
            acc[e] += v.w * wv.w;
        }
        uint2 u;
        u.x = pkh(__float2half_rn(v.x), __float2half_rn(v.y));
        u.y = pkh(__float2half_rn(v.z), __float2half_rn(v.w));
        reinterpret_cast<uint2*>(g_xh)[(size_t)t * (DIM / 4) + i4] = u;
    }

#pragma unroll
    for (int e = 0; e < NEXP; e++) {
        float s = acc[e];
        s += __shfl_xor_sync(0xffffffffu, s, 16);
        s += __shfl_xor_sync(0xffffffffu, s, 8);
        s += __shfl_xor_sync(0xffffffffu, s, 4);
        s += __shfl_xor_sync(0xffffffffu, s, 2);
        s += __shfl_xor_sync(0xffffffffu, s, 1);
        acc[e] = s;
    }

    if (lane == 0) {
        float v[NEXP];
#pragma unroll
        for (int e = 0; e < NEXP; e++) v[e] = acc[e] + bg[e];
        int e0 = 0;
#pragma unroll
        for (int e = 1; e < NEXP; e++) if (v[e] > v[e0]) e0 = e;
        int e1 = (e0 == 0) ? 1 : 0;
#pragma unroll
        for (int e = 0; e < NEXP; e++) if (e != e0 && v[e] > v[e1]) e1 = e;
        float d  = expf(v[e1] - v[e0]);
        float w0 = 1.f / (1.f + d);
        float w1 = 1.f - w0;

        unsigned p0 = atomicAdd(&g_cnt[e0], 1u);
        g_tok[e0 * NTOK + p0] = t;
        g_wt [e0 * NTOK + p0] = w0;
        unsigned p1 = atomicAdd(&g_cnt[e1], 1u);
        g_tok[e1 * NTOK + p1] = t | (1 << 16);
        g_wt [e1 * NTOK + p1] = w1;
    }
}

// ---------------- kernel 3: grouped expert GEMM, fp16, 8 warps x (64x32) ----------------
__global__ __launch_bounds__(256, 2) void moe_gemm_mma(const float* __restrict__ bias) {
    extern __shared__ char smem[];
    const int e = blockIdx.y;
    const unsigned cnt = g_cnt[e];
    const int m0 = blockIdx.x * BM;
    if ((unsigned)m0 >= cnt) return;
    const int valid = min(BM, (int)(cnt - m0));
    const int n0 = blockIdx.z * BN;

    const int tid  = threadIdx.x;
    const int lane = tid & 31, wid = tid >> 5;
    const int warp_m = wid & 1, warp_n = wid >> 1;   // 2m x 4n
    const uint32_t sb = smem_u32(smem);

    int*   s_tok  = reinterpret_cast<int*>(smem + OFF_TOK);
    int*   s_dst  = reinterpret_cast<int*>(smem + OFF_DST);
    float* s_wt   = reinterpret_cast<float*>(smem + OFF_WT);
    float* s_bias = reinterpret_cast<float*>(smem + OFF_BIAS);

    if (tid < 128) {
        int raw = 0; float w = 0.f;
        if (tid < valid) { raw = g_tok[e * NTOK + m0 + tid]; w = g_wt[e * NTOK + m0 + tid]; }
        int t = raw & 0xFFFF;
        s_tok[tid] = t;
        s_dst[tid] = (raw >> 16) * NTOK + t;
        s_wt [tid] = w;
        s_bias[tid] = bias[e * DIM + n0 + tid];
    }
    __syncthreads();

    // ---- per-thread loader: 4 chunks of 16B per stage (1024 chunks / 256 thr)
    const char* lsrc[4];
    uint32_t    ldst[4];
#pragma unroll
    for (int j = 0; j < 4; j++) {
        const int i    = tid + j * 256;
        const int kind = i >> 9;           // 0 = A, 1 = B
        const int rem  = i & 511;
        const int row  = rem >> 2;
        const int c    = rem & 3;          // 16B chunk within 64B row
        const __half* base;
        if (kind == 0)
            base = g_xh + (size_t)s_tok[row] * DIM + c * 8;
        else
            base = g_wh + (size_t)e * DIM * DIM + (size_t)(n0 + row) * DIM + c * 8;
        lsrc[j] = reinterpret_cast<const char*>(base);
        ldst[j] = sb + OFF_TILES + kind * TILE_B + row * ROWB + c * 16;
    }

    // ---- ldmatrix base addresses (buf 0, k16 = 0); add bufOff + k16*32 at use
    const int aRow = ((lane >> 3) & 1) * 8 + (lane & 7);
    const int aCol = ((lane >> 4) & 1) * 8;
    const int bRow = ((lane >> 4) & 1) * 8 + (lane & 7);
    const int bCol = ((lane >> 3) & 1) * 8;
    uint32_t aAddr[4], bAddr[2];
#pragma unroll
    for (int mt = 0; mt < 4; mt++)
        aAddr[mt] = sb + OFF_TILES + (warp_m * 64 + mt * 16 + aRow) * ROWB + aCol * 2;
#pragma unroll
    for (int pr = 0; pr < 2; pr++)
        bAddr[pr] = sb + OFF_TILES + TILE_B + (warp_n * 32 + pr * 16 + bRow) * ROWB + bCol * 2;

    float acc[4][4][4];
#pragma unroll
    for (int a = 0; a < 4; a++)
#pragma unroll
        for (int b2 = 0; b2 < 4; b2++)
#pragma unroll
            for (int c = 0; c < 4; c++) acc[a][b2][c] = 0.f;

    // ---- prologue: 4 stages in flight
#pragma unroll
    for (int ks = 0; ks < 4; ks++) {
        const uint32_t bo = ks * BUF_B;
#pragma unroll
        for (int j = 0; j < 4; j++) cpasync16(ldst[j] + bo, lsrc[j] + ks * (BK * 2));
        cp_commit();
    }

    // ---- mainloop: one barrier per 32-K stage
    for (int ks = 0; ks < KSTEPS; ks++) {
        cp_wait3();
        __syncthreads();
        if (ks + 4 < KSTEPS) {
            const uint32_t bo = ((ks + 4) % STAGES) * BUF_B;
#pragma unroll
            for (int j = 0; j < 4; j++) cpasync16(ldst[j] + bo, lsrc[j] + (ks + 4) * (BK * 2));
        }
        cp_commit();

        const uint32_t bufOff = (ks % STAGES) * BUF_B;
#pragma unroll
        for (int k16 = 0; k16 < 2; k16++) {
            const uint32_t ko = bufOff + k16 * 32;
            uint32_t ah[4][4];
#pragma unroll
            for (int mt = 0; mt < 4; mt++) ldmx4(ah[mt], aAddr[mt] + ko);
#pragma unroll
            for (int pr = 0; pr < 2; pr++) {
                uint32_t bh[4];
                ldmx4(bh, bAddr[pr] + ko);
                const int nt = pr * 2;
#pragma unroll
                for (int mt = 0; mt < 4; mt++) {
                    mma16816h(acc[mt][nt],     ah[mt], bh[0], bh[1]);
                    mma16816h(acc[mt][nt + 1], ah[mt], bh[2], bh[3]);
                }
            }
        }
    }

    // ---- epilogue: out = w * (acc + bias) -> scratch (deterministic slot)
    const int g  = lane >> 2;
    const int tg = lane & 3;
#pragma unroll
    for (int mt = 0; mt < 4; mt++) {
        const int r0 = warp_m * 64 + mt * 16 + g;
        const int r1 = r0 + 8;
        const bool ok0 = r0 < valid, ok1 = r1 < valid;
        const float w0 = s_wt[r0], w1 = s_wt[r1];
        const size_t d0 = (size_t)s_dst[r0] * DIM;
        const size_t d1 = (size_t)s_dst[r1] * DIM;
#pragma unroll
        for (int nt = 0; nt < 4; nt++) {
            const int cloc = warp_n * 32 + nt * 8 + tg * 2;
            const int col  = n0 + cloc;
            const float b0v = s_bias[cloc], b1v = s_bias[cloc + 1];
            if (ok0) {
                float2 o;
                o.x = w0 * (acc[mt][nt][0] + b0v);
                o.y = w0 * (acc[mt][nt][1] + b1v);
                *reinterpret_cast<float2*>(g_scr + d0 + col) = o;
            }
            if (ok1) {
                float2 o;
                o.x = w1 * (acc[mt][nt][2] + b0v);
                o.y = w1 * (acc[mt][nt][3] + b1v);
                *reinterpret_cast<float2*>(g_scr + d1 + col) = o;
            }
        }
    }
}

// ---------------- kernel 4: combine ----------------
__global__ void combine_kernel(float* __restrict__ out) {
    const float4* s = reinterpret_cast<const float4*>(g_scr);
    float4* o = reinterpret_cast<float4*>(out);
    const int total = NTOK * (DIM / 4);
    for (int i = blockIdx.x * blockDim.x + threadIdx.x; i < total; i += gridDim.x * blockDim.x) {
        float4 a = s[i];
        float4 b = s[i + total];
        float4 r;
        r.x = a.x + b.x; r.y = a.y + b.y; r.z = a.z + b.z; r.w = a.w + b.w;
        o[i] = r;
    }
}

// ---------------- launch ----------------
extern "C" void kernel_launch(void* const* d_in, const int* in_sizes, int n_in,
                              void* d_out, int out_size) {
    const float* x  = (const float*)d_in[0];
    const float* W  = (const float*)d_in[1];
    const float* b  = (const float*)d_in[2];
    const float* Wg = (const float*)d_in[3];
    const float* bg = (const float*)d_in[4];
    float* out = (float*)d_out;

    cudaFuncSetAttribute(moe_gemm_mma, cudaFuncAttributeMaxDynamicSharedMemorySize, GEMM_SMEM);

    reset_kernel<<<1, 32>>>();
    prepw_kernel<<<(NEXP * DIM * DIM / 4) / 256, 256>>>(W);
    gate_kernel<<<NTOK / 8, 256>>>(x, Wg, bg);
    dim3 grid(NTOK / BM, NEXP, DIM / BN);
    moe_gemm_mma<<<grid, 256, GEMM_SMEM>>>(b);
    combine_kernel<<<8192, 256>>>(out);
}

// round 9
// speedup vs baseline: 2.8093x; 1.0525x over previous
#include <cuda_runtime.h>
#include <cuda_bf16.h>
#include <cuda_fp16.h>
#include <cstdint>

#define NTOK 65536
#define DIM  512
#define NEXP 8

// GEMM tile: BM=128 x BN=128, BK=32, 5-stage cp.async, fp16 1-pass,
// 8 warps (2m x 4n), warp tile 64x32.
#define BM 128
#define BN 128
#define BK 32
#define KSTEPS (DIM / BK)          // 16
#define STAGES 5
#define ROWB 80                    // bytes per smem tile row (32 fp16 + 16B pad)
#define TILE_B (128 * ROWB)        // 10240 : one tile (A or B)
#define BUF_B  (2 * TILE_B)        // 20480 : one stage (A + B)
#define OFF_TOK   0
#define OFF_DST   512
#define OFF_WT    1024
#define OFF_BIAS  1536
#define OFF_TILES 2048
#define GEMM_SMEM (OFF_TILES + STAGES * BUF_B)   // 104448 -> 2 CTAs/SM

// ---------------- device scratch ----------------
__device__ unsigned  g_cnt[NEXP];
__device__ int       g_tok[NEXP * NTOK];
__device__ float     g_wt [NEXP * NTOK];
__device__ __half    g_xh[(size_t)NTOK * DIM];
__device__ __half    g_wh[(size_t)NEXP * DIM * DIM];
__device__ __half    g_scrh[(size_t)2 * NTOK * DIM];   // fp16 contributions

// ---------------- helpers ----------------
__device__ __forceinline__ uint32_t pkh(__half a, __half b) {
    return (uint32_t)__half_as_ushort(a) | ((uint32_t)__half_as_ushort(b) << 16);
}
__device__ __forceinline__ uint32_t smem_u32(const void* p) {
    return (uint32_t)__cvta_generic_to_shared(p);
}
__device__ __forceinline__ void cpasync16(uint32_t dst, const void* src) {
    asm volatile("cp.async.cg.shared.global [%0], [%1], 16;\n" :: "r"(dst), "l"(src));
}
__device__ __forceinline__ void cp_commit() { asm volatile("cp.async.commit_group;\n" ::: "memory"); }
__device__ __forceinline__ void cp_wait3()  { asm volatile("cp.async.wait_group 3;\n" ::: "memory"); }

__device__ __forceinline__ void ldmx4(uint32_t* r, uint32_t addr) {
    asm volatile("ldmatrix.sync.aligned.m8n8.x4.shared.b16 {%0,%1,%2,%3}, [%4];\n"
                 : "=r"(r[0]), "=r"(r[1]), "=r"(r[2]), "=r"(r[3]) : "r"(addr));
}
__device__ __forceinline__ void mma16816h(float* c, const uint32_t* a, uint32_t b0, uint32_t b1) {
    asm volatile("mma.sync.aligned.m16n8k16.row.col.f32.f16.f16.f32 "
                 "{%0,%1,%2,%3}, {%4,%5,%6,%7}, {%8,%9}, {%0,%1,%2,%3};\n"
                 : "+f"(c[0]), "+f"(c[1]), "+f"(c[2]), "+f"(c[3])
                 : "r"(a[0]), "r"(a[1]), "r"(a[2]), "r"(a[3]), "r"(b0), "r"(b1));
}

// ---------------- kernel 1: W -> fp16 (+ counter reset folded in) ----------------
__global__ void prepw_kernel(const float* __restrict__ W) {
    if (blockIdx.x == 0 && threadIdx.x < NEXP) g_cnt[threadIdx.x] = 0;
    int idx = blockIdx.x * blockDim.x + threadIdx.x;
    float4 v = reinterpret_cast<const float4*>(W)[idx];
    uint2 u;
    u.x = pkh(__float2half_rn(v.x), __float2half_rn(v.y));
    u.y = pkh(__float2half_rn(v.z), __float2half_rn(v.w));
    reinterpret_cast<uint2*>(g_wh)[idx] = u;
}

// ---------------- kernel 2: gate (scores, top2, softmax, buckets) + x -> fp16 ----------------
__global__ __launch_bounds__(256) void gate_kernel(const float* __restrict__ x,
                                                   const float* __restrict__ Wg,
                                                   const float* __restrict__ bg) {
    __shared__ float sWg[NEXP * DIM];
    const int tid = threadIdx.x;
    for (int i = tid; i < NEXP * DIM / 4; i += 256)
        reinterpret_cast<float4*>(sWg)[i] = reinterpret_cast<const float4*>(Wg)[i];
    __syncthreads();

    const int wid = tid >> 5, lane = tid & 31;
    const int t = blockIdx.x * 8 + wid;

    const float4* xr = reinterpret_cast<const float4*>(x) + (size_t)t * (DIM / 4);
    float acc[NEXP];
#pragma unroll
    for (int e = 0; e < NEXP; e++) acc[e] = 0.f;

#pragma unroll
    for (int j = 0; j < 4; j++) {
        const int i4 = lane + 32 * j;
        float4 v = xr[i4];
#pragma unroll
        for (int e = 0; e < NEXP; e++) {
            float4 wv = reinterpret_cast<const float4*>(sWg)[e * (DIM / 4) + i4];
            acc[e] += v.x * wv.x;
            acc[e] += v.y * wv.y;
            acc[e] += v.z * wv.z;
            acc[e] += v.w * wv.w;
        }
        uint2 u;
        u.x = pkh(__float2half_rn(v.x), __float2half_rn(v.y));
        u.y = pkh(__float2half_rn(v.z), __float2half_rn(v.w));
        reinterpret_cast<uint2*>(g_xh)[(size_t)t * (DIM / 4) + i4] = u;
    }

#pragma unroll
    for (int e = 0; e < NEXP; e++) {
        float s = acc[e];
        s += __shfl_xor_sync(0xffffffffu, s, 16);
        s += __shfl_xor_sync(0xffffffffu, s, 8);
        s += __shfl_xor_sync(0xffffffffu, s, 4);
        s += __shfl_xor_sync(0xffffffffu, s, 2);
        s += __shfl_xor_sync(0xffffffffu, s, 1);
        acc[e] = s;
    }

    if (lane == 0) {
        float v[NEXP];
#pragma unroll
        for (int e = 0; e < NEXP; e++) v[e] = acc[e] + bg[e];
        int e0 = 0;
#pragma unroll
        for (int e = 1; e < NEXP; e++) if (v[e] > v[e0]) e0 = e;
        int e1 = (e0 == 0) ? 1 : 0;
#pragma unroll
        for (int e = 0; e < NEXP; e++) if (e != e0 && v[e] > v[e1]) e1 = e;
        float d  = expf(v[e1] - v[e0]);
        float w0 = 1.f / (1.f + d);
        float w1 = 1.f - w0;

        unsigned p0 = atomicAdd(&g_cnt[e0], 1u);
        g_tok[e0 * NTOK + p0] = t;
        g_wt [e0 * NTOK + p0] = w0;
        unsigned p1 = atomicAdd(&g_cnt[e1], 1u);
        g_tok[e1 * NTOK + p1] = t | (1 << 16);
        g_wt [e1 * NTOK + p1] = w1;
    }
}

// ---------------- kernel 3: grouped expert GEMM, fp16, 8 warps x (64x32) ----------------
__global__ __launch_bounds__(256, 2) void moe_gemm_mma(const float* __restrict__ bias) {
    extern __shared__ char smem[];
    const int e = blockIdx.y;
    const unsigned cnt = g_cnt[e];
    const int m0 = blockIdx.x * BM;
    if ((unsigned)m0 >= cnt) return;
    const int valid = min(BM, (int)(cnt - m0));
    const int n0 = blockIdx.z * BN;

    const int tid  = threadIdx.x;
    const int lane = tid & 31, wid = tid >> 5;
    const int warp_m = wid & 1, warp_n = wid >> 1;   // 2m x 4n
    const uint32_t sb = smem_u32(smem);

    int*   s_tok  = reinterpret_cast<int*>(smem + OFF_TOK);
    int*   s_dst  = reinterpret_cast<int*>(smem + OFF_DST);
    float* s_wt   = reinterpret_cast<float*>(smem + OFF_WT);
    float* s_bias = reinterpret_cast<float*>(smem + OFF_BIAS);

    if (tid < 128) {
        int raw = 0; float w = 0.f;
        if (tid < valid) { raw = g_tok[e * NTOK + m0 + tid]; w = g_wt[e * NTOK + m0 + tid]; }
        int t = raw & 0xFFFF;
        s_tok[tid] = t;
        s_dst[tid] = (raw >> 16) * NTOK + t;
        s_wt [tid] = w;
        s_bias[tid] = bias[e * DIM + n0 + tid];
    }
    __syncthreads();

    // ---- per-thread loader: 4 chunks of 16B per stage (1024 chunks / 256 thr)
    const char* lsrc[4];
    uint32_t    ldst[4];
#pragma unroll
    for (int j = 0; j < 4; j++) {
        const int i    = tid + j * 256;
        const int kind = i >> 9;           // 0 = A, 1 = B
        const int rem  = i & 511;
        const int row  = rem >> 2;
        const int c    = rem & 3;          // 16B chunk within 64B row
        const __half* base;
        if (kind == 0)
            base = g_xh + (size_t)s_tok[row] * DIM + c * 8;
        else
            base = g_wh + (size_t)e * DIM * DIM + (size_t)(n0 + row) * DIM + c * 8;
        lsrc[j] = reinterpret_cast<const char*>(base);
        ldst[j] = sb + OFF_TILES + kind * TILE_B + row * ROWB + c * 16;
    }

    // ---- ldmatrix base addresses (buf 0, k16 = 0); add bufOff + k16*32 at use
    const int aRow = ((lane >> 3) & 1) * 8 + (lane & 7);
    const int aCol = ((lane >> 4) & 1) * 8;
    const int bRow = ((lane >> 4) & 1) * 8 + (lane & 7);
    const int bCol = ((lane >> 3) & 1) * 8;
    uint32_t aAddr[4], bAddr[2];
#pragma unroll
    for (int mt = 0; mt < 4; mt++)
        aAddr[mt] = sb + OFF_TILES + (warp_m * 64 + mt * 16 + aRow) * ROWB + aCol * 2;
#pragma unroll
    for (int pr = 0; pr < 2; pr++)
        bAddr[pr] = sb + OFF_TILES + TILE_B + (warp_n * 32 + pr * 16 + bRow) * ROWB + bCol * 2;

    float acc[4][4][4];
#pragma unroll
    for (int a = 0; a < 4; a++)
#pragma unroll
        for (int b2 = 0; b2 < 4; b2++)
#pragma unroll
            for (int c = 0; c < 4; c++) acc[a][b2][c] = 0.f;

    // ---- prologue: 4 stages in flight
#pragma unroll
    for (int ks = 0; ks < 4; ks++) {
        const uint32_t bo = ks * BUF_B;
#pragma unroll
        for (int j = 0; j < 4; j++) cpasync16(ldst[j] + bo, lsrc[j] + ks * (BK * 2));
        cp_commit();
    }

    // ---- mainloop: one barrier per 32-K stage
    for (int ks = 0; ks < KSTEPS; ks++) {
        cp_wait3();
        __syncthreads();
        if (ks + 4 < KSTEPS) {
            const uint32_t bo = ((ks + 4) % STAGES) * BUF_B;
#pragma unroll
            for (int j = 0; j < 4; j++) cpasync16(ldst[j] + bo, lsrc[j] + (ks + 4) * (BK * 2));
        }
        cp_commit();

        const uint32_t bufOff = (ks % STAGES) * BUF_B;
#pragma unroll
        for (int k16 = 0; k16 < 2; k16++) {
            const uint32_t ko = bufOff + k16 * 32;
            uint32_t ah[4][4];
#pragma unroll
            for (int mt = 0; mt < 4; mt++) ldmx4(ah[mt], aAddr[mt] + ko);
#pragma unroll
            for (int pr = 0; pr < 2; pr++) {
                uint32_t bh[4];
                ldmx4(bh, bAddr[pr] + ko);
                const int nt = pr * 2;
#pragma unroll
                for (int mt = 0; mt < 4; mt++) {
                    mma16816h(acc[mt][nt],     ah[mt], bh[0], bh[1]);
                    mma16816h(acc[mt][nt + 1], ah[mt], bh[2], bh[3]);
                }
            }
        }
    }

    // ---- epilogue: scr = half( w * (acc + bias) )  (deterministic slot)
    const int g  = lane >> 2;
    const int tg = lane & 3;
#pragma unroll
    for (int mt = 0; mt < 4; mt++) {
        const int r0 = warp_m * 64 + mt * 16 + g;
        const int r1 = r0 + 8;
        const bool ok0 = r0 < valid, ok1 = r1 < valid;
        const float w0 = s_wt[r0], w1 = s_wt[r1];
        const size_t d0 = (size_t)s_dst[r0] * DIM;
        const size_t d1 = (size_t)s_dst[r1] * DIM;
#pragma unroll
        for (int nt = 0; nt < 4; nt++) {
            const int cloc = warp_n * 32 + nt * 8 + tg * 2;
            const int col  = n0 + cloc;
            const float b0v = s_bias[cloc], b1v = s_bias[cloc + 1];
            if (ok0) {
                __half2 h = __floats2half2_rn(w0 * (acc[mt][nt][0] + b0v),
                                              w0 * (acc[mt][nt][1] + b1v));
                *reinterpret_cast<__half2*>(g_scrh + d0 + col) = h;
            }
            if (ok1) {
                __half2 h = __floats2half2_rn(w1 * (acc[mt][nt][2] + b0v),
                                              w1 * (acc[mt][nt][3] + b1v));
                *reinterpret_cast<__half2*>(g_scrh + d1 + col) = h;
            }
        }
    }
}

// ---------------- kernel 4: combine (fp16 scr -> fp32 out) ----------------
__global__ void combine_kernel(float* __restrict__ out) {
    const uint4* s = reinterpret_cast<const uint4*>(g_scrh);   // 8 halves per uint4
    float4* o = reinterpret_cast<float4*>(out);
    const int total = NTOK * (DIM / 8);
    for (int i = blockIdx.x * blockDim.x + threadIdx.x; i < total; i += gridDim.x * blockDim.x) {
        uint4 a = s[i];
        uint4 b = s[i + total];
        const __half2* ah = reinterpret_cast<const __half2*>(&a);
        const __half2* bh = reinterpret_cast<const __half2*>(&b);
        float4 o0, o1;
        float2 p0 = __half22float2(ah[0]), q0 = __half22float2(bh[0]);
        float2 p1 = __half22float2(ah[1]), q1 = __half22float2(bh[1]);
        float2 p2 = __half22float2(ah[2]), q2 = __half22float2(bh[2]);
        float2 p3 = __half22float2(ah[3]), q3 = __half22float2(bh[3]);
        o0.x = p0.x + q0.x; o0.y = p0.y + q0.y;
        o0.z = p1.x + q1.x; o0.w = p1.y + q1.y;
        o1.x = p2.x + q2.x; o1.y = p2.y + q2.y;
        o1.z = p3.x + q3.x; o1.w = p3.y + q3.y;
        o[i * 2]     = o0;
        o[i * 2 + 1] = o1;
    }
}

// ---------------- launch ----------------
extern "C" void kernel_launch(void* const* d_in, const int* in_sizes, int n_in,
                              void* d_out, int out_size) {
    const float* x  = (const float*)d_in[0];
    const float* W  = (const float*)d_in[1];
    const float* b  = (const float*)d_in[2];
    const float* Wg = (const float*)d_in[3];
    const float* bg = (const float*)d_in[4];
    float* out = (float*)d_out;

    cudaFuncSetAttribute(moe_gemm_mma, cudaFuncAttributeMaxDynamicSharedMemorySize, GEMM_SMEM);

    prepw_kernel<<<(NEXP * DIM * DIM / 4) / 256, 256>>>(W);
    gate_kernel<<<NTOK / 8, 256>>>(x, Wg, bg);
    dim3 grid(NTOK / BM, NEXP, DIM / BN);
    moe_gemm_mma<<<grid, 256, GEMM_SMEM>>>(b);
    combine_kernel<<<8192, 256>>>(out);
}